// round 9
// baseline (speedup 1.0000x reference)
#include <cuda_runtime.h>
#include <cuda_fp16.h>

#define NB 2048
#define NT 128
#define NS 256
#define NV 29
#define NE 32
#define NH 64
#define EP 17      // fp32 encoder row pitch in float4 (16 data + 1 pad)
#define G  2
#define THREADS 512

// SMEM: f4: encs 8704 | xbuf 2*80=160          = 141,824 B
//       uint2: enc16 8192                       =  65,536 B
//       float: buf 512 | buf2 1024 | cb 128 | reds 16 | fcbs 32 = 6,848 B
//       int:   ybuf 256                         =   1,024 B
#define SMEM_BYTES ((8704 + 160) * 16 + 8192 * 8 + (512 + 1024 + 128 + 16 + 32) * 4 + 256 * 4)
static_assert(SMEM_BYTES <= 227 * 1024, "smem over budget");

__device__ __forceinline__ float2 ffma2(float2 a, float2 b, float2 c) {
    union U { float2 f; unsigned long long u; };
    U ua, ub, uc, d;
    ua.f = a; ub.f = b; uc.f = c;
    asm("fma.rn.f32x2 %0, %1, %2, %3;" : "=l"(d.u) : "l"(ua.u), "l"(ub.u), "l"(uc.u));
    return d.f;
}
__device__ __forceinline__ float fast_sigmoid(float x) {
    return __frcp_rn(1.f + __expf(-x));
}
__device__ __forceinline__ float fast_tanh(float x) {
    return fmaf(-2.f, __frcp_rn(__expf(2.f * x) + 1.f), 1.f);
}

__global__ __launch_bounds__(THREADS, 1) void decoder_kernel(
    const int* __restrict__ y, const float* __restrict__ h0,
    const float* __restrict__ c0, const float* __restrict__ enc,
    const float* __restrict__ emb, const float* __restrict__ Wih,
    const float* __restrict__ Whh, const float* __restrict__ bih,
    const float* __restrict__ bhh, const float* __restrict__ fcW,
    const float* __restrict__ fcb, float* __restrict__ out)
{
    const int tid  = threadIdx.x;
    const int lane = tid & 31;
    const int warp = tid >> 5;
    const int b0   = blockIdx.x * G;

    extern __shared__ float4 sm4[];
    float4* encs  = sm4;                           // [G][NS][EP] fp32 (scores)
    float4* xb0   = encs + G * NS * EP;            // parity-0 x: [G][40] = ctx 0..15|emb 16..23|h 24..39
    float4* xb1   = xb0 + G * 40;                  // parity-1 x
    uint2*  enc16 = (uint2*)(xb1 + G * 40);        // [G][NS][16] fp16 (ctx pass)
    float*  buf   = (float*)(enc16 + G * NS * 16); // [G][256] exp(scores)
    float*  buf2  = buf + G * 256;                 // [2 halves][G][256]
    float*  cb    = buf2 + 1024;                   // [G][64]
    float*  reds  = cb + G * NH;                   // [16]
    float*  fcbs  = reds + 16;                     // [NV]
    int*    ybuf  = (int*)(fcbs + 32);             // [G][NT]

    // ---- one-time staging ----
    for (int i = tid; i < G * NS * 16; i += THREADS) {
        const int gg = i >> 12, r = (i >> 4) & 255, k = i & 15;
        const float4 v = ((const float4*)(enc + (size_t)(b0 + gg) * NS * NH))[r * 16 + k];
        encs[(gg * NS + r) * EP + k] = v;
        const __half2 ha = __floats2half2_rn(v.x, v.y);
        const __half2 hb = __floats2half2_rn(v.z, v.w);
        uint2 u;
        u.x = *(const unsigned*)&ha;
        u.y = *(const unsigned*)&hb;
        enc16[(gg * NS + r) * 16 + k] = u;
    }
    if (tid < NV) fcbs[tid] = fcb[tid];
    if (tid < G * NT) {
        const int gg = tid >> 7, tt = tid & 127;
        ybuf[gg * NT + tt] = y[(b0 + gg) * NT + tt];
    }
    __syncthreads();   // ybuf ready for the emb fetch below
    if (tid < G * NH) {           // h0 into both buffers, c0, zero ctx parity-0
        const int gg = tid >> 6, j = tid & 63;
        float* x0f = (float*)xb0;
        float* x1f = (float*)xb1;
        const float hv = h0[(b0 + gg) * NH + j];
        x0f[gg * 160 + 96 + j] = hv;
        x1f[gg * 160 + 96 + j] = hv;
        cb[gg * 64 + j] = c0[(b0 + gg) * NH + j];
        x0f[gg * 160 + j] = 0.f;  // zero ctx slot parity-0 (used at t=0)
    }
    if (tid >= 256 && tid < 288) {   // emb(t=0) into both buffers
        const int i = tid - 256, gg = i >> 4, k2 = i & 15;
        const int yv = ybuf[gg * NT];
        const float4 ev = ((const float4*)emb)[yv * 8 + (k2 & 7)];
        ((k2 < 8) ? xb0 : xb1)[gg * 40 + 16 + (k2 & 7)] = ev;
    }

    // ---- gate weights -> regs. x cols: [ctx(16) | emb(8) | h(16)]
    // half0 = cols 0..19 (ctx + emb f4 0..3); half1 = cols 20..39 (emb f4 4..7 + h)
    const int row  = tid & 255;
    const int half = tid >> 8;
    float4 w[20];
    {
        const float4* wi4 = (const float4*)Wih + row * 24;
        const float4* wh4 = (const float4*)Whh + row * 16;
        if (half == 0) {
            #pragma unroll
            for (int j = 0; j < 16; j++) w[j] = wi4[8 + j];      // ctx cols
            #pragma unroll
            for (int j = 0; j < 4; j++)  w[16 + j] = wi4[j];     // emb f4 0..3
        } else {
            #pragma unroll
            for (int j = 0; j < 4; j++)  w[j] = wi4[4 + j];      // emb f4 4..7
            #pragma unroll
            for (int j = 0; j < 16; j++) w[4 + j] = wh4[j];      // h cols
        }
    }
    const float bsum = (half == 0) ? (bih[row] + bhh[row]) : 0.f;

    // ---- fcW -> regs ----
    const int s  = tid & 255;
    const int v  = s >> 3;
    const int l  = s & 7;
    float4 fw0, fw1, fw2, fw3;
    if (v < NV) {
        const float4* fc4 = (const float4*)fcW + v * 32;
        fw0 = fc4[l]; fw1 = fc4[8 + l]; fw2 = fc4[16 + l]; fw3 = fc4[24 + l];
    } else {
        fw0 = fw1 = fw2 = fw3 = make_float4(0.f, 0.f, 0.f, 0.f);
    }
    __syncthreads();

    // fixed addressing
    const int g = tid >> 8;
    const float4* erow = encs + (g * NS + s) * EP;          // P1 score row
    const int k4 = tid & 15, sgl = (tid >> 4) & 15;         // P3 mapping
    const float* at   = buf + g * 256 + sgl * 16;
    const uint2* ec16 = enc16 + (g * 256 + sgl * 16) * 16 + k4;

    for (int t = 0; t < NT; t++) {
        float4* xp = (t & 1) ? xb1 : xb0;        // current-parity x
        float4* xo = (t & 1) ? xb0 : xb1;        // other parity (zeroed for t+1)
        float*  xpf = (float*)xp;
        float*  xof = (float*)xo;

        // ---- P1: scores (fp32) -> exp -> p to SMEM + warp partial sums ----
        {
            const float4* hv4 = xp + g * 40 + 24;
            float2 a0 = make_float2(0.f, 0.f), a1 = make_float2(0.f, 0.f);
            #pragma unroll
            for (int k = 0; k < 16; k++) {
                const float4 e = erow[k], hv = hv4[k];
                a0 = ffma2(make_float2(e.x, e.y), make_float2(hv.x, hv.y), a0);
                a1 = ffma2(make_float2(e.z, e.w), make_float2(hv.z, hv.w), a1);
            }
            const float p = __expf(a0.x + a0.y + a1.x + a1.y);
            buf[g * 256 + s] = p;
            float sum = p;
            #pragma unroll
            for (int o = 16; o; o >>= 1) sum += __shfl_xor_sync(~0u, sum, o);
            if (lane == 0) reds[warp] = sum;
        }
        __syncthreads();  // B1

        // ---- P3: normalized context partials via shared atomics (fp16 enc) ----
        {
            float zs = reds[g * 8];
            #pragma unroll
            for (int i = 1; i < 8; i++) zs += reds[g * 8 + i];
            const float invZ = __frcp_rn(zs);

            float2 cXY = make_float2(0.f, 0.f), cZW = make_float2(0.f, 0.f);
            #pragma unroll
            for (int i = 0; i < 16; i++) {
                const float pi = at[i];
                const uint2 u = ec16[i * 16];
                const float2 e01 = __half22float2(*(const __half2*)&u.x);
                const float2 e23 = __half22float2(*(const __half2*)&u.y);
                cXY = ffma2(e01, make_float2(pi, pi), cXY);
                cZW = ffma2(e23, make_float2(pi, pi), cZW);
            }
            cXY.x += __shfl_xor_sync(~0u, cXY.x, 16);
            cXY.y += __shfl_xor_sync(~0u, cXY.y, 16);
            cZW.x += __shfl_xor_sync(~0u, cZW.x, 16);
            cZW.y += __shfl_xor_sync(~0u, cZW.y, 16);
            if (lane < 16) {
                float* dst = xpf + g * 160 + 4 * k4;   // ctx floats 0..63
                atomicAdd(dst + 0, cXY.x * invZ);
                atomicAdd(dst + 1, cXY.y * invZ);
                atomicAdd(dst + 2, cZW.x * invZ);
                atomicAdd(dst + 3, cZW.y * invZ);
            }
        }
        __syncthreads();  // B2

        // ---- P5: gates, both halves in ONE parallel window ----
        {
            const float4* x0 = xp + half * 20;        // group 0
            const float4* x1 = xp + 40 + half * 20;   // group 1
            float2 p0 = make_float2(0.f, 0.f), q0 = make_float2(0.f, 0.f);
            float2 p1 = make_float2(0.f, 0.f), q1 = make_float2(0.f, 0.f);
            #pragma unroll
            for (int j = 0; j < 20; j++) {
                const float4 wv = w[j];
                const float4 xa = x0[j];
                p0 = ffma2(make_float2(wv.x, wv.y), make_float2(xa.x, xa.y), p0);
                q0 = ffma2(make_float2(wv.z, wv.w), make_float2(xa.z, xa.w), q0);
                const float4 xb = x1[j];
                p1 = ffma2(make_float2(wv.x, wv.y), make_float2(xb.x, xb.y), p1);
                q1 = ffma2(make_float2(wv.z, wv.w), make_float2(xb.z, xb.w), q1);
            }
            buf2[half * 512 + row]       = p0.x + p0.y + q0.x + q0.y + bsum;
            buf2[half * 512 + 256 + row] = p1.x + p1.y + q1.x + q1.y + bsum;
        }
        __syncthreads();  // B3

        // ---- W4: LSTM (tid<128) || zero next ctx (tid 128..255) || emb t+1 (tid 256..287) ----
        if (tid < G * NH) {
            const int gg = tid >> 6, j = tid & 63;
            const float* g0p = buf2 + gg * 256;
            const float* g1p = buf2 + 512 + gg * 256;
            const float ig = g0p[j]       + g1p[j];
            const float fg = g0p[64 + j]  + g1p[64 + j];
            const float gt = g0p[128 + j] + g1p[128 + j];
            const float og = g0p[192 + j] + g1p[192 + j];
            const float cn = fmaf(fast_sigmoid(fg), cb[gg * 64 + j],
                                  fast_sigmoid(ig) * fast_tanh(gt));
            cb[gg * 64 + j] = cn;
            const float hn = fast_sigmoid(og) * fast_tanh(cn);
            xpf[(tid >> 6) * 160 + 96 + (tid & 63)] = hn;   // for P7 now
            xof[(tid >> 6) * 160 + 96 + (tid & 63)] = hn;   // for P1/P5 at t+1
        } else if (tid < 256) {
            const int i = tid - 128;
            xof[(i >> 6) * 160 + (i & 63)] = 0.f;           // zero ctx slot for t+1
        } else if (tid < 288 && t + 1 < NT) {
            const int i = tid - 256, gg = i >> 4, k2 = i & 15;
            const int yv = ybuf[gg * NT + t + 1];
            const float4 ev = ((const float4*)emb)[yv * 8 + (k2 & 7)];
            ((k2 < 8) ? xb0 : xb1)[gg * 40 + 16 + (k2 & 7)] = ev;
        }
        __syncthreads();  // B4

        // ---- P7: logits, fcW from registers (reads h 24..39, ctx 0..15 of xp) ----
        {
            float acc = 0.f;
            if (v < NV) {
                const float4 h0v = xp[g * 40 + 24 + l];
                const float4 h1v = xp[g * 40 + 32 + l];
                const float4 c0v = xp[g * 40 + l];
                const float4 c1v = xp[g * 40 + 8 + l];
                float2 a2 = make_float2(0.f, 0.f);
                a2 = ffma2(make_float2(fw0.x, fw0.y), make_float2(h0v.x, h0v.y), a2);
                a2 = ffma2(make_float2(fw0.z, fw0.w), make_float2(h0v.z, h0v.w), a2);
                a2 = ffma2(make_float2(fw1.x, fw1.y), make_float2(h1v.x, h1v.y), a2);
                a2 = ffma2(make_float2(fw1.z, fw1.w), make_float2(h1v.z, h1v.w), a2);
                a2 = ffma2(make_float2(fw2.x, fw2.y), make_float2(c0v.x, c0v.y), a2);
                a2 = ffma2(make_float2(fw2.z, fw2.w), make_float2(c0v.z, c0v.w), a2);
                a2 = ffma2(make_float2(fw3.x, fw3.y), make_float2(c1v.x, c1v.y), a2);
                a2 = ffma2(make_float2(fw3.z, fw3.w), make_float2(c1v.z, c1v.w), a2);
                acc = a2.x + a2.y;
            }
            acc += __shfl_down_sync(~0u, acc, 4, 8);
            acc += __shfl_down_sync(~0u, acc, 2, 8);
            acc += __shfl_down_sync(~0u, acc, 1, 8);
            if (v < NV && l == 0)
                out[((size_t)(b0 + g) * NT + t) * NV + v] = acc + fcbs[v];
        }
        // wrap: P1(t+1) writes buf/reds — last read in P3(t), >=2 barriers back. Safe.
    }
}

extern "C" void kernel_launch(void* const* d_in, const int* in_sizes, int n_in,
                              void* d_out, int out_size) {
    const int*   y    = (const int*)  d_in[0];
    const float* h0   = (const float*)d_in[1];
    const float* c0   = (const float*)d_in[2];
    const float* enc  = (const float*)d_in[3];
    const float* emb  = (const float*)d_in[4];
    const float* Wih  = (const float*)d_in[5];
    const float* Whh  = (const float*)d_in[6];
    const float* bih  = (const float*)d_in[7];
    const float* bhh  = (const float*)d_in[8];
    const float* fcW  = (const float*)d_in[9];
    const float* fcb  = (const float*)d_in[10];
    float* out = (float*)d_out;

    cudaFuncSetAttribute(decoder_kernel,
                         cudaFuncAttributeMaxDynamicSharedMemorySize, SMEM_BYTES);
    decoder_kernel<<<NB / G, THREADS, SMEM_BYTES>>>(y, h0, c0, enc, emb, Wih, Whh,
                                                    bih, bhh, fcW, fcb, out);
}

// round 14
// speedup vs baseline: 1.0898x; 1.0898x over previous
#include <cuda_runtime.h>
#include <cuda_fp16.h>

#define NB 2048
#define NT 128
#define NS 256
#define NV 29
#define NE 32
#define NH 64
#define EP 17      // fp32 encoder row pitch in float4 (16 data + 1 pad)
#define G  2
#define THREADS 512

// SMEM: f4: encs 8704 | xh 80 | cpart 256 = 144,640 B
//       uint2: enc16 8192                 =  65,536 B
//       float: buf 512 | buf2 1024 | cb 128 | reds 16 | fcbs 32 = 6,848 B
#define SMEM_BYTES ((8704 + 80 + 256) * 16 + 8192 * 8 + (512 + 1024 + 128 + 16 + 32) * 4)
static_assert(SMEM_BYTES == 217024, "layout audit");
static_assert(SMEM_BYTES <= 227 * 1024, "smem over budget");

__device__ __forceinline__ float2 ffma2(float2 a, float2 b, float2 c) {
    union U { float2 f; unsigned long long u; };
    U ua, ub, uc, d;
    ua.f = a; ub.f = b; uc.f = c;
    asm("fma.rn.f32x2 %0, %1, %2, %3;" : "=l"(d.u) : "l"(ua.u), "l"(ub.u), "l"(uc.u));
    return d.f;
}
__device__ __forceinline__ float fast_sigmoid(float x) {
    return __frcp_rn(1.f + __expf(-x));
}
__device__ __forceinline__ float fast_tanh(float x) {
    return fmaf(-2.f, __frcp_rn(__expf(2.f * x) + 1.f), 1.f);
}

__global__ __launch_bounds__(THREADS, 1) void decoder_kernel(
    const int* __restrict__ y, const float* __restrict__ h0,
    const float* __restrict__ c0, const float* __restrict__ enc,
    const float* __restrict__ emb, const float* __restrict__ Wih,
    const float* __restrict__ Whh, const float* __restrict__ bih,
    const float* __restrict__ bhh, const float* __restrict__ fcW,
    const float* __restrict__ fcb, float* __restrict__ out)
{
    const int tid  = threadIdx.x;
    const int g    = tid >> 8;        // batch element within CTA
    const int s    = tid & 255;
    const int lane = tid & 31;
    const int wrp  = tid >> 5;
    const int b0   = blockIdx.x * G;

    extern __shared__ float4 sm4[];
    float4* encs  = sm4;                           // [G][NS][EP] fp32 (scores pass)
    float4* xh4   = encs + G * NS * EP;            // [G][40]: emb 0..7 | ctx 8..23 | h 24..39
    float4* cpart = xh4 + G * 40;                  // [G][8][16]
    uint2*  enc16 = (uint2*)(cpart + 256);         // [G][NS][16] fp16 (ctx pass)
    float*  buf   = (float*)(enc16 + G * NS * 16); // [G][256] exp(scores)
    float*  buf2  = buf + G * 256;                 // [2 halves][G][256]
    float*  cb    = buf2 + 1024;                   // [G][64]
    float*  reds  = cb + G * NH;                   // [16]
    float*  fcbs  = reds + 16;                     // [NV]
    float*  xh    = (float*)xh4;

    // ---- one-time staging (fp32 + fp16 copies of enc) ----
    for (int i = tid; i < G * NS * 16; i += THREADS) {
        const int gg = i >> 12, r = (i >> 4) & 255, k = i & 15;
        const float4 v = ((const float4*)(enc + (size_t)(b0 + gg) * NS * NH))[r * 16 + k];
        encs[(gg * NS + r) * EP + k] = v;
        const __half2 ha = __floats2half2_rn(v.x, v.y);
        const __half2 hb = __floats2half2_rn(v.z, v.w);
        uint2 u;
        u.x = *(const unsigned*)&ha;
        u.y = *(const unsigned*)&hb;
        enc16[(gg * NS + r) * 16 + k] = u;
    }
    if (tid < NV) fcbs[tid] = fcb[tid];
    if (tid < G * NH) {
        const int gg = tid >> 6, j = tid & 63;
        xh[gg * 160 + 96 + j] = h0[(b0 + gg) * NH + j];
        cb[gg * 64 + j]       = c0[(b0 + gg) * NH + j];
    }

    // ---- gate weights -> regs: CHAMPION mapping (row = tid&255, half = tid>>8)
    // x layout cols: [emb(8) | ctx(16) | h(16)]
    // half0 = x cols 0..19 (emb + ctx f4 0..11) = wi[0..19]
    // half1 = x cols 20..39 (ctx f4 12..15 + h) = wi[20..23] + wh[0..15]
    const int row  = tid & 255;
    const int half = tid >> 8;
    float4 w[20];
    {
        const float4* wi = (const float4*)Wih + row * 24;
        const float4* wh = (const float4*)Whh + row * 16;
        if (half == 0) {
            #pragma unroll
            for (int j = 0; j < 20; j++) w[j] = wi[j];
        } else {
            #pragma unroll
            for (int j = 0; j < 4; j++)  w[j] = wi[20 + j];
            #pragma unroll
            for (int j = 0; j < 16; j++) w[4 + j] = wh[j];
        }
    }
    const float bsum = (half == 0) ? (bih[row] + bhh[row]) : 0.f;  // bias added ONCE

    // ---- fcW -> regs ----
    const int v = s >> 3;
    const int l = tid & 7;
    float4 fw0, fw1, fw2, fw3;
    if (v < NV) {
        const float4* fc4 = (const float4*)fcW + v * 32;
        fw0 = fc4[l]; fw1 = fc4[8 + l]; fw2 = fc4[16 + l]; fw3 = fc4[24 + l];
    } else {
        fw0 = fw1 = fw2 = fw3 = make_float4(0.f, 0.f, 0.f, 0.f);
    }
    __syncthreads();

    for (int t = 0; t < NT; t++) {
        // ---- P1: scores + exp + warp partial sums (fp32, packed f32x2) ----
        {
            const float4* er  = encs + (g * NS + s) * EP;
            const float4* hv4 = xh4 + g * 40 + 24;
            float2 a0 = make_float2(0.f, 0.f), a1 = make_float2(0.f, 0.f);
            #pragma unroll
            for (int k = 0; k < 16; k++) {
                const float4 e = er[k], hv = hv4[k];
                a0 = ffma2(make_float2(e.x, e.y), make_float2(hv.x, hv.y), a0);
                a1 = ffma2(make_float2(e.z, e.w), make_float2(hv.z, hv.w), a1);
            }
            const float p = __expf(a0.x + a0.y + a1.x + a1.y);
            buf[g * 256 + s] = p;
            float sum = p;
            #pragma unroll
            for (int o = 16; o; o >>= 1) sum += __shfl_xor_sync(~0u, sum, o);
            if (lane == 0) reds[wrp] = sum;
        }
        __syncthreads();  // B1

        // ---- P3: context partials (fp16 enc), pre-reduced by shfl_xor(16) ----
        {
            const int k4 = tid & 15, sg = (tid >> 4) & 15;
            const float* at   = buf + g * 256 + sg * 16;
            const uint2* ec16 = enc16 + (g * 256 + sg * 16) * 16 + k4;
            float2 aXY = make_float2(0.f, 0.f), aZW = make_float2(0.f, 0.f);
            #pragma unroll
            for (int i = 0; i < 16; i++) {
                const float wa = at[i];
                const uint2 u = ec16[i * 16];
                const float2 e01 = __half22float2(*(const __half2*)&u.x);
                const float2 e23 = __half22float2(*(const __half2*)&u.y);
                aXY = ffma2(e01, make_float2(wa, wa), aXY);
                aZW = ffma2(e23, make_float2(wa, wa), aZW);
            }
            aXY.x += __shfl_xor_sync(~0u, aXY.x, 16);
            aXY.y += __shfl_xor_sync(~0u, aXY.y, 16);
            aZW.x += __shfl_xor_sync(~0u, aZW.x, 16);
            aZW.y += __shfl_xor_sync(~0u, aZW.y, 16);
            if ((sg & 1) == 0)
                cpart[(g * 8 + (sg >> 1)) * 16 + k4] =
                    make_float4(aXY.x, aXY.y, aZW.x, aZW.y);
        }
        // ---- P3b: embedding fetch (8 threads per group) ----
        if (s >= 64 && s < 72) {
            const int k  = tid & 7;
            const int yv = y[(b0 + g) * NT + t];
            xh4[g * 40 + k] = ((const float4*)emb)[yv * 8 + k];
        }
        __syncthreads();  // B2

        // ---- P4: context reduce + normalize (inv folded in) ----
        if (tid < 32) {
            const int gg = tid >> 4, k4 = tid & 15;
            float ssum = reds[gg * 8];
            #pragma unroll
            for (int i = 1; i < 8; i++) ssum += reds[gg * 8 + i];
            const float iv = __frcp_rn(ssum);
            const float4* cp = cpart + gg * 8 * 16 + k4;
            float4 a = cp[0];
            #pragma unroll
            for (int sgp = 1; sgp < 8; sgp++) {
                const float4 vv = cp[sgp * 16];
                a.x += vv.x; a.y += vv.y; a.z += vv.z; a.w += vv.w;
            }
            xh4[gg * 40 + 8 + k4] = make_float4(a.x * iv, a.y * iv, a.z * iv, a.w * iv);
        }
        __syncthreads();  // B3

        // ---- P5: gates; all xh reads uniform per warp (broadcast) ----
        {
            const float4* x0 = xh4 + half * 20;        // group 0
            const float4* x1 = xh4 + 40 + half * 20;   // group 1
            float2 p0 = make_float2(0.f, 0.f), q0 = make_float2(0.f, 0.f);
            float2 p1 = make_float2(0.f, 0.f), q1 = make_float2(0.f, 0.f);
            #pragma unroll
            for (int j = 0; j < 20; j++) {
                const float4 wv = w[j];
                const float4 xa = x0[j];
                p0 = ffma2(make_float2(wv.x, wv.y), make_float2(xa.x, xa.y), p0);
                q0 = ffma2(make_float2(wv.z, wv.w), make_float2(xa.z, xa.w), q0);
                const float4 xb = x1[j];
                p1 = ffma2(make_float2(wv.x, wv.y), make_float2(xb.x, xb.y), p1);
                q1 = ffma2(make_float2(wv.z, wv.w), make_float2(xb.z, xb.w), q1);
            }
            buf2[half * 512 + row]       = p0.x + p0.y + q0.x + q0.y + bsum;
            buf2[half * 512 + 256 + row] = p1.x + p1.y + q1.x + q1.y + bsum;
        }
        __syncthreads();  // B4

        // ---- P6: combine halves + LSTM elementwise (i,f,g,o) ----
        if (tid < G * NH) {
            const int gg = tid >> 6, j = tid & 63;
            const float* g0p = buf2 + gg * 256;
            const float* g1p = buf2 + 512 + gg * 256;
            const float ig = g0p[j]       + g1p[j];
            const float fg = g0p[64 + j]  + g1p[64 + j];
            const float gt = g0p[128 + j] + g1p[128 + j];
            const float og = g0p[192 + j] + g1p[192 + j];
            const float cn = fmaf(fast_sigmoid(fg), cb[gg * 64 + j],
                                  fast_sigmoid(ig) * fast_tanh(gt));
            cb[gg * 64 + j] = cn;
            xh[gg * 160 + 96 + j] = fast_sigmoid(og) * fast_tanh(cn);
        }
        __syncthreads();  // B5

        // ---- P7: logits, fcW from registers ----
        {
            float acc = 0.f;
            if (v < NV) {
                const float4 h0v = xh4[g * 40 + 24 + l];  // h lo
                const float4 h1v = xh4[g * 40 + 32 + l];  // h hi
                const float4 c2v = xh4[g * 40 + 8 + l];   // ctx lo
                const float4 c3v = xh4[g * 40 + 16 + l];  // ctx hi
                float2 a2 = make_float2(0.f, 0.f);
                a2 = ffma2(make_float2(fw0.x, fw0.y), make_float2(h0v.x, h0v.y), a2);
                a2 = ffma2(make_float2(fw0.z, fw0.w), make_float2(h0v.z, h0v.w), a2);
                a2 = ffma2(make_float2(fw1.x, fw1.y), make_float2(h1v.x, h1v.y), a2);
                a2 = ffma2(make_float2(fw1.z, fw1.w), make_float2(h1v.z, h1v.w), a2);
                a2 = ffma2(make_float2(fw2.x, fw2.y), make_float2(c2v.x, c2v.y), a2);
                a2 = ffma2(make_float2(fw2.z, fw2.w), make_float2(c2v.z, c2v.w), a2);
                a2 = ffma2(make_float2(fw3.x, fw3.y), make_float2(c3v.x, c3v.y), a2);
                a2 = ffma2(make_float2(fw3.z, fw3.w), make_float2(c3v.z, c3v.w), a2);
                acc = a2.x + a2.y;
            }
            acc += __shfl_down_sync(~0u, acc, 4, 8);
            acc += __shfl_down_sync(~0u, acc, 2, 8);
            acc += __shfl_down_sync(~0u, acc, 1, 8);
            if (v < NV && l == 0)
                out[((size_t)(b0 + g) * NT + t) * NV + v] = acc + fcbs[v];
        }
        // no trailing barrier: next-iter writes ordered behind B1/B2 (as in R3)
    }
}

extern "C" void kernel_launch(void* const* d_in, const int* in_sizes, int n_in,
                              void* d_out, int out_size) {
    const int*   y    = (const int*)  d_in[0];
    const float* h0   = (const float*)d_in[1];
    const float* c0   = (const float*)d_in[2];
    const float* enc  = (const float*)d_in[3];
    const float* emb  = (const float*)d_in[4];
    const float* Wih  = (const float*)d_in[5];
    const float* Whh  = (const float*)d_in[6];
    const float* bih  = (const float*)d_in[7];
    const float* bhh  = (const float*)d_in[8];
    const float* fcW  = (const float*)d_in[9];
    const float* fcb  = (const float*)d_in[10];
    float* out = (float*)d_out;

    cudaFuncSetAttribute(decoder_kernel,
                         cudaFuncAttributeMaxDynamicSharedMemorySize, SMEM_BYTES);
    decoder_kernel<<<NB / G, THREADS, SMEM_BYTES>>>(y, h0, c0, enc, emb, Wih, Whh,
                                                    bih, bhh, fcW, fcb, out);
}